// round 17
// baseline (speedup 1.0000x reference)
#include <cuda_runtime.h>
#include <cuda_bf16.h>
#include <cstdint>

// Problem constants
#define BB 1024
#define TT 512
#define DD 128

// Scratch (legal: __device__ globals).
static __device__ float g_xg[134217728];  // B*T*256 : x@Wg_x + gate_bias
static __device__ float g_xc[67108864];   // B*T*128 : x@Wc_x + cand_bias
// x-side W transposed [384][128] K-major, bf16 hi/lo (for pre_mma)
static __device__ __nv_bfloat16 g_wthi[49152];
static __device__ __nv_bfloat16 g_wtlo[49152];
// h-side W transposed [384][128] K-major, bf16 hi/lo (for rec HMMA)
static __device__ __nv_bfloat16 g_whhi[49152];
static __device__ __nv_bfloat16 g_whlo[49152];

// ---------------- helpers ----------------
__device__ __forceinline__ uint32_t smem_u32(const void* p) {
    uint32_t a;
    asm("{ .reg .u64 t; cvta.to.shared.u64 t, %1; cvt.u32.u64 %0, t; }" : "=r"(a) : "l"(p));
    return a;
}
__device__ __forceinline__ void ldsm4(uint32_t* r, uint32_t addr) {
    asm volatile("ldmatrix.sync.aligned.m8n8.x4.shared.b16 {%0,%1,%2,%3}, [%4];"
                 : "=r"(r[0]), "=r"(r[1]), "=r"(r[2]), "=r"(r[3]) : "r"(addr));
}
__device__ __forceinline__ void mma_bf16(float* d, const uint32_t* a, const uint32_t* b) {
    asm volatile(
        "mma.sync.aligned.m16n8k16.row.col.f32.bf16.bf16.f32 "
        "{%0,%1,%2,%3}, {%4,%5,%6,%7}, {%8,%9}, {%0,%1,%2,%3};"
        : "+f"(d[0]), "+f"(d[1]), "+f"(d[2]), "+f"(d[3])
        : "r"(a[0]), "r"(a[1]), "r"(a[2]), "r"(a[3]), "r"(b[0]), "r"(b[1]));
}
__device__ __forceinline__ void cpa16(uint32_t s, const void* g) {
    asm volatile("cp.async.cg.shared.global [%0], [%1], 16;"
                 :: "r"(s), "l"(__cvta_generic_to_global(g)) : "memory");
}
#define CP_COMMIT() asm volatile("cp.async.commit_group;" ::: "memory")
#define CP_WAIT0()  asm volatile("cp.async.wait_group 0;" ::: "memory")

// pack two fp32 -> bf16x2 (vHI -> upper half, vLO -> lower half)
__device__ __forceinline__ uint32_t pack_bf2(float vHI, float vLO) {
    uint32_t r;
    asm("cvt.rn.bf16x2.f32 %0, %1, %2;" : "=r"(r) : "f"(vHI), "f"(vLO));
    return r;
}
__device__ __forceinline__ float bflo(uint32_t p) { return __uint_as_float(p << 16); }
__device__ __forceinline__ float bfhi(uint32_t p) { return __uint_as_float(p & 0xFFFF0000u); }

__device__ __forceinline__ float frcp(float x) {
    float r;
    asm("rcp.approx.f32 %0, %1;" : "=f"(r) : "f"(x));
    return r;
}

// ---------------------------------------------------------------------------
// Prep: transpose both halves of W to [384][128] K-major, bf16 hi/lo split.
// ---------------------------------------------------------------------------
__global__ void prep_w(const float* __restrict__ gk, const float* __restrict__ ck) {
    int n = blockIdx.x, k = threadIdx.x;
    float vx = (n < 256) ? gk[k * 256 + n] : ck[k * 128 + (n - 256)];
    __nv_bfloat16 hx = __float2bfloat16(vx);
    g_wthi[n * 128 + k] = hx;
    g_wtlo[n * 128 + k] = __float2bfloat16(vx - __bfloat162float(hx));
    float vh = (n < 256) ? gk[(128 + k) * 256 + n] : ck[(128 + k) * 128 + (n - 256)];
    __nv_bfloat16 hh = __float2bfloat16(vh);
    g_whhi[n * 128 + k] = hh;
    g_whlo[n * 128 + k] = __float2bfloat16(vh - __bfloat162float(hh));
}

// ---------------------------------------------------------------------------
// Kernel 1: hoisted x-GEMM on HMMA, bf16x3 split, cp.async double-buffered B.
// NOW 512 threads (16 warps = 8M x 2N, warp tile 16x64) for 4 warps/SMSP.
// Dead tiles (t0 >= seqlen[b]) skipped.
// smem: bias[384f] | Ahi 128x272 | Alo | Bbuf0(hi,lo) | Bbuf1(hi,lo)
// ---------------------------------------------------------------------------
#define A_HI_OFF 1536
#define A_LO_OFF (A_HI_OFF + 34816)
#define B_BUF0   (A_LO_OFF + 34816)
#define B_BUF1   (B_BUF0 + 69632)
#define PRE_SMEM (B_BUF1 + 69632)

__global__ void __launch_bounds__(512) pre_mma(
    const float* __restrict__ X,
    const float* __restrict__ gb, const float* __restrict__ cb,
    const int* __restrict__ seqlen)
{
    extern __shared__ char smc[];
    const uint32_t sb = smem_u32(smc);
    float* biasS = reinterpret_cast<float*>(smc);
    const int tid  = threadIdx.x;
    const int lane = tid & 31;
    const int wid  = tid >> 5;
    const int wm   = wid & 7;        // 8 M-groups x 16 rows
    const int wn   = wid >> 3;       // 2 N-groups x 64 cols
    const int m0   = blockIdx.x * 128;

    {
        const int b  = m0 >> 9;
        const int t0 = m0 & 511;
        if (t0 >= __ldg(&seqlen[b])) return;
    }

    if (tid < 256) biasS[tid] = gb[tid];
    if (tid < 128) biasS[256 + tid] = cb[tid];

    // ---- issue B tile nt=0 via cp.async (row = tid>>2, quarter = tid&3) ----
    {
        const int row = tid >> 2;
        const int q   = tid & 3;
        uint32_t dHi = sb + B_BUF0 + row * 272 + q * 64;
        uint32_t dLo = dHi + 34816;
        const __nv_bfloat16* sH = &g_wthi[row * 128 + q * 32];
        const __nv_bfloat16* sL = &g_wtlo[row * 128 + q * 32];
        #pragma unroll
        for (int j = 0; j < 4; j++) {
            cpa16(dHi + j * 16, sH + j * 8);
            cpa16(dLo + j * 16, sL + j * 8);
        }
        CP_COMMIT();
    }

    // ---- A tile: fp32 -> bf16 hi/lo, padded rows (272B) ----
    {
        const int row = tid >> 2;
        const int q   = tid & 3;
        const float* xr = &X[(size_t)(m0 + row) * 128 + q * 32];
        char* Ahi = smc + A_HI_OFF + row * 272 + q * 64;
        char* Alo = smc + A_LO_OFF + row * 272 + q * 64;
        #pragma unroll
        for (int j = 0; j < 8; j++) {
            float4 v = *reinterpret_cast<const float4*>(&xr[j * 4]);
            __nv_bfloat162 h01 = __floats2bfloat162_rn(v.x, v.y);
            __nv_bfloat162 h23 = __floats2bfloat162_rn(v.z, v.w);
            __nv_bfloat162 l01 = __floats2bfloat162_rn(v.x - __bfloat162float(h01.x),
                                                       v.y - __bfloat162float(h01.y));
            __nv_bfloat162 l23 = __floats2bfloat162_rn(v.z - __bfloat162float(h23.x),
                                                       v.w - __bfloat162float(h23.y));
            *reinterpret_cast<uint2*>(Ahi + j * 8) =
                make_uint2(*reinterpret_cast<uint32_t*>(&h01), *reinterpret_cast<uint32_t*>(&h23));
            *reinterpret_cast<uint2*>(Alo + j * 8) =
                make_uint2(*reinterpret_cast<uint32_t*>(&l01), *reinterpret_cast<uint32_t*>(&l23));
        }
    }

    const uint32_t aRow = sb + A_HI_OFF + (wm * 16 + (lane & 15)) * 272 + (lane >> 4) * 16;
    const uint32_t ALO_D = A_LO_OFF - A_HI_OFF;

    for (int nt = 0; nt < 3; nt++) {
        CP_WAIT0();
        __syncthreads();
        const uint32_t bufC = (nt & 1) ? B_BUF1 : B_BUF0;
        if (nt < 2) {
            const int row = tid >> 2;
            const int q   = tid & 3;
            const uint32_t bufN = (nt & 1) ? B_BUF0 : B_BUF1;
            uint32_t dHi = sb + bufN + row * 272 + q * 64;
            uint32_t dLo = dHi + 34816;
            const __nv_bfloat16* sH = &g_wthi[((nt + 1) * 128 + row) * 128 + q * 32];
            const __nv_bfloat16* sL = &g_wtlo[((nt + 1) * 128 + row) * 128 + q * 32];
            #pragma unroll
            for (int j = 0; j < 4; j++) {
                cpa16(dHi + j * 16, sH + j * 8);
                cpa16(dLo + j * 16, sL + j * 8);
            }
            CP_COMMIT();
        }

        const uint32_t bRowB = sb + bufC
            + (wn * 64 + (lane & 7) + (lane >> 4) * 8) * 272 + ((lane >> 3) & 1) * 16;

        float d[8][4];
        #pragma unroll
        for (int nf = 0; nf < 8; nf++)
            #pragma unroll
            for (int e = 0; e < 4; e++) d[nf][e] = 0.0f;

        #pragma unroll
        for (int pass = 0; pass < 3; pass++) {
            const uint32_t aOff = (pass == 2) ? ALO_D : 0u;
            const uint32_t bOff = (pass == 1) ? 34816u : 0u;
            #pragma unroll
            for (int k16 = 0; k16 < 8; k16++) {
                uint32_t a0[4];
                ldsm4(a0, aRow + aOff + k16 * 32);
                #pragma unroll
                for (int g = 0; g < 4; g++) {
                    uint32_t bb[4];
                    ldsm4(bb, bRowB + bOff + g * (16 * 272) + k16 * 32);
                    mma_bf16(d[2 * g],     a0, bb);
                    mma_bf16(d[2 * g + 1], a0, bb + 2);
                }
            }
        }

        {
            const int grp = lane >> 2;
            const int qid = lane & 3;
            #pragma unroll
            for (int nf = 0; nf < 8; nf++) {
                const int cg = wn * 64 + nf * 8 + qid * 2;
                float2 bv = *reinterpret_cast<const float2*>(&biasS[nt * 128 + cg]);
                const int r0 = m0 + wm * 16 + grp;
                float2 v0 = make_float2(d[nf][0] + bv.x, d[nf][1] + bv.y);
                float2 v1 = make_float2(d[nf][2] + bv.x, d[nf][3] + bv.y);
                if (nt < 2) {
                    *reinterpret_cast<float2*>(&g_xg[(size_t)r0 * 256 + nt * 128 + cg]) = v0;
                    *reinterpret_cast<float2*>(&g_xg[(size_t)(r0 + 8) * 256 + nt * 128 + cg]) = v1;
                } else {
                    *reinterpret_cast<float2*>(&g_xc[(size_t)r0 * 128 + cg]) = v0;
                    *reinterpret_cast<float2*>(&g_xc[(size_t)(r0 + 8) * 128 + cg]) = v1;
                }
            }
        }
    }
}

// ---------------------------------------------------------------------------
// Kernel 2: recurrent scan on HMMA, hi/lo packed in M. Paired-reciprocal
// activations (2 sigmoids / 2 tanhs share one rcp.approx).
// ---------------------------------------------------------------------------
#define WCHI 0
#define WCLO 34816
#define HHI  69632
#define HLO  71808
#define RHHI 73984
#define RHLO 76160
#define HS   78336
#define US   82560
#define ATTS 86784
#define LENO 103168
#define REC_SMEM 103200

__global__ void __launch_bounds__(512, 1) rec_kernel(
    const float* __restrict__ att,
    const int*   __restrict__ seqlen,
    float* __restrict__ out)
{
    extern __shared__ char smc[];
    const uint32_t sb = smem_u32(smc);
    float* hS   = reinterpret_cast<float*>(smc + HS);    // [8][132] fp32
    float* uS   = reinterpret_cast<float*>(smc + US);    // [8][132] fp32
    float* attS = reinterpret_cast<float*>(smc + ATTS);  // [8][512]
    int*   lenS = reinterpret_cast<int*>(smc + LENO);    // [8]

    const int tid  = threadIdx.x;
    const int lane = tid & 31;
    const int w    = tid >> 5;
    const int b0   = blockIdx.x * 8;

    // stage cand h-side W hi/lo into smem [128 n][272B rows]
    for (int idx = tid; idx < 8192; idx += 512) {
        int rown = idx >> 6, kp = (idx & 63) * 2;
        *reinterpret_cast<uint32_t*>(smc + WCHI + rown * 272 + kp * 2) =
            *reinterpret_cast<const uint32_t*>(&g_whhi[(256 + rown) * 128 + kp]);
        *reinterpret_cast<uint32_t*>(smc + WCLO + rown * 272 + kp * 2) =
            *reinterpret_cast<const uint32_t*>(&g_whlo[(256 + rown) * 128 + kp]);
    }
    // att preload: attS[i][t]
    for (int idx = tid; idx < 4096; idx += 512) {
        int i = idx >> 9, t = idx & 511;
        attS[idx] = att[(b0 + i) * TT + t];
    }
    for (int idx = tid; idx < 1056; idx += 512) hS[idx] = 0.0f;
    for (int idx = tid; idx < 544; idx += 512) {
        reinterpret_cast<uint32_t*>(smc + HHI)[idx] = 0u;
        reinterpret_cast<uint32_t*>(smc + HLO)[idx] = 0u;
    }
    if (tid < 8) lenS[tid] = seqlen[b0 + tid];
    __syncthreads();

    int tmax = 0;
    #pragma unroll
    for (int i = 0; i < 8; i++) tmax = max(tmax, lenS[i]);

    const int row  = lane >> 2;        // 0..7 (batch row within CTA)
    const int colp = (lane & 3) * 2;   // col pair base within n-tile
    const int cw   = w * 16;           // gate col base (w<8: r cols, w>=8: u cols)
    const bool isr = (w < 8);
    const int ccol = w * 8 + colp;     // cand col

    // ---- preload gate W fragments (persistent in registers) ----
    uint32_t wgh[2][8][2], wgl[2][8][2];
    #pragma unroll
    for (int nt = 0; nt < 2; nt++)
        #pragma unroll
        for (int kt = 0; kt < 8; kt++) {
            int n = cw + nt * 8 + (lane >> 2);
            int base = n * 128 + kt * 16 + colp;
            wgh[nt][kt][0] = *reinterpret_cast<const uint32_t*>(&g_whhi[base]);
            wgh[nt][kt][1] = *reinterpret_cast<const uint32_t*>(&g_whhi[base + 8]);
            wgl[nt][kt][0] = *reinterpret_cast<const uint32_t*>(&g_whlo[base]);
            wgl[nt][kt][1] = *reinterpret_cast<const uint32_t*>(&g_whlo[base + 8]);
        }

    // fused hi/lo ldsm.x4 bases: matrices {0,1}=hi{k0-7,k8-15}, {2,3}=lo
    const uint32_t laneRH = (lane & 7) * 272 + ((lane >> 3) & 1) * 16;
    const uint32_t aAg4 = sb + (lane < 16 ? HHI  : HLO)  + laneRH;
    const uint32_t aAc4 = sb + (lane < 16 ? RHHI : RHLO) + laneRH;
    const uint32_t bAc4 = sb + (lane < 16 ? WCHI : WCLO)
        + (w * 8 + (lane & 7)) * 272 + ((lane >> 3) & 1) * 16;

    const size_t mrB = (size_t)(b0 + row) * TT;
    // pipeline: loads for step t issued at top of step t-1 (here: t=0 preload)
    float2 nxg0 = *reinterpret_cast<const float2*>(&g_xg[mrB * 256 + cw + colp]);
    float2 nxg1 = *reinterpret_cast<const float2*>(&g_xg[mrB * 256 + cw + 8 + colp]);
    float2 nxc  = *reinterpret_cast<const float2*>(&g_xc[mrB * 128 + ccol]);

    for (int t = 0; t < tmax; t++) {
        const float2 xg0 = nxg0, xg1 = nxg1, xc = nxc;
        {   // issue next step's loads (hidden under this whole step)
            const int tn = (t + 1 < tmax) ? t + 1 : t;
            nxg0 = *reinterpret_cast<const float2*>(&g_xg[(mrB + tn) * 256 + cw + colp]);
            nxg1 = *reinterpret_cast<const float2*>(&g_xg[(mrB + tn) * 256 + cw + 8 + colp]);
            nxc  = *reinterpret_cast<const float2*>(&g_xc[(mrB + tn) * 128 + ccol]);
        }

        // ---- gate MMA: A = [h_hi | h_lo] packed in M; 2 MMA per (nt,kt) ----
        float dgA[2][4] = {{0.f, 0.f, 0.f, 0.f}, {0.f, 0.f, 0.f, 0.f}};
        float dgB[2][4] = {{0.f, 0.f, 0.f, 0.f}, {0.f, 0.f, 0.f, 0.f}};
        #pragma unroll
        for (int kt = 0; kt < 8; kt++) {
            uint32_t g4[4];
            ldsm4(g4, aAg4 + kt * 32);
            uint32_t af[4] = {g4[0], g4[2], g4[1], g4[3]};
            float (*dg)[4] = (kt & 1) ? dgB : dgA;
            #pragma unroll
            for (int nt = 0; nt < 2; nt++) {
                mma_bf16(dg[nt], af, wgh[nt][kt]);
                mma_bf16(dg[nt], af, wgl[nt][kt]);
            }
        }
        // ---- gate epilogue: paired-rcp sigmoid ----
        {
            float x0 = dgA[0][0] + dgA[0][2] + dgB[0][0] + dgB[0][2] + xg0.x;
            float x1 = dgA[0][1] + dgA[0][3] + dgB[0][1] + dgB[0][3] + xg0.y;
            float x2 = dgA[1][0] + dgA[1][2] + dgB[1][0] + dgB[1][2] + xg1.x;
            float x3 = dgA[1][1] + dgA[1][3] + dgB[1][1] + dgB[1][3] + xg1.y;
            float e0 = __expf(-x0), e1 = __expf(-x1);
            float e2 = __expf(-x2), e3 = __expf(-x3);
            float f0 = 1.0f + e0, f1 = 1.0f + e1, f2 = 1.0f + e2, f3 = 1.0f + e3;
            float r01 = frcp(f0 * f1), r23 = frcp(f2 * f3);
            float s0 = f1 * r01, s1 = f0 * r01;
            float s2 = f3 * r23, s3 = f2 * r23;
            if (isr) {
                int c0 = cw + colp, c1 = cw + 8 + colp;
                float2 ha = *reinterpret_cast<const float2*>(&hS[row * 132 + c0]);
                float2 hb = *reinterpret_cast<const float2*>(&hS[row * 132 + c1]);
                float r0 = s0 * ha.x, r1 = s1 * ha.y;
                float r2 = s2 * hb.x, r3 = s3 * hb.y;
                uint32_t p0 = pack_bf2(r1, r0);
                uint32_t p1 = pack_bf2(r3, r2);
                uint32_t q0 = pack_bf2(r1 - bfhi(p0), r0 - bflo(p0));
                uint32_t q1 = pack_bf2(r3 - bfhi(p1), r2 - bflo(p1));
                *reinterpret_cast<uint32_t*>(smc + RHHI + row * 272 + c0 * 2) = p0;
                *reinterpret_cast<uint32_t*>(smc + RHHI + row * 272 + c1 * 2) = p1;
                *reinterpret_cast<uint32_t*>(smc + RHLO + row * 272 + c0 * 2) = q0;
                *reinterpret_cast<uint32_t*>(smc + RHLO + row * 272 + c1 * 2) = q1;
            } else {
                int c0 = cw - 128 + colp;
                *reinterpret_cast<float2*>(&uS[row * 132 + c0])     = make_float2(s0, s1);
                *reinterpret_cast<float2*>(&uS[row * 132 + c0 + 8]) = make_float2(s2, s3);
            }
        }
        __syncthreads();

        // ---- cand MMA: A = [rh_hi | rh_lo] packed; 2 MMA per kt ----
        float dcA[4] = {0.f, 0.f, 0.f, 0.f};
        float dcB[4] = {0.f, 0.f, 0.f, 0.f};
        #pragma unroll
        for (int kt = 0; kt < 8; kt++) {
            uint32_t a4[4], b4[4];
            ldsm4(a4, aAc4 + kt * 32);
            ldsm4(b4, bAc4 + kt * 32);
            uint32_t af[4] = {a4[0], a4[2], a4[1], a4[3]};
            mma_bf16(dcA, af, b4);       // *Wc_hi
            mma_bf16(dcB, af, b4 + 2);   // *Wc_lo
        }
        // ---- cand epilogue: paired-rcp tanh + update + mask + store ----
        {
            float y0 = dcA[0] + dcA[2] + dcB[0] + dcB[2] + xc.x;
            float y1 = dcA[1] + dcA[3] + dcB[1] + dcB[3] + xc.y;
            y0 = fminf(20.0f, fmaxf(-20.0f, y0));
            y1 = fminf(20.0f, fmaxf(-20.0f, y1));
            float E0 = __expf(2.0f * y0), E1 = __expf(2.0f * y1);
            float g0 = E0 + 1.0f, g1 = E1 + 1.0f;
            float rr = frcp(g0 * g1);
            float c0 = (E0 - 1.0f) * g1 * rr;
            float c1 = (E1 - 1.0f) * g0 * rr;
            float2 u2 = *reinterpret_cast<const float2*>(&uS[row * 132 + ccol]);
            float2 h2 = *reinterpret_cast<const float2*>(&hS[row * 132 + ccol]);
            float a = attS[row * 512 + t];
            int len = lenS[row];
            float uu0 = (1.0f - a) * u2.x;
            float uu1 = (1.0f - a) * u2.y;
            float n0 = uu0 * h2.x + (1.0f - uu0) * c0;
            float n1 = uu1 * h2.y + (1.0f - uu1) * c1;
            bool mk = (t < len);
            *reinterpret_cast<float2*>(&out[(mrB + t) * 128 + ccol]) =
                mk ? make_float2(n0, n1) : make_float2(0.0f, 0.0f);
            if (mk) {
                *reinterpret_cast<float2*>(&hS[row * 132 + ccol]) = make_float2(n0, n1);
                uint32_t p = pack_bf2(n1, n0);
                uint32_t q = pack_bf2(n1 - bfhi(p), n0 - bflo(p));
                *reinterpret_cast<uint32_t*>(smc + HHI + row * 272 + ccol * 2) = p;
                *reinterpret_cast<uint32_t*>(smc + HLO + row * 272 + ccol * 2) = q;
            }
        }
        __syncthreads();
    }

    // dynamic_rnn zeroes outputs past the sequence length; t >= tmax >= len[i]
    for (int t = tmax; t < TT; t++) {
        for (int idx = tid; idx < 1024; idx += 512) {
            int i = idx >> 7, d = idx & 127;
            out[((size_t)(b0 + i) * TT + t) * 128 + d] = 0.0f;
        }
    }
}

// ---------------------------------------------------------------------------
extern "C" void kernel_launch(void* const* d_in, const int* in_sizes, int n_in,
                              void* d_out, int out_size) {
    const float* x   = (const float*)d_in[0];   // rnn_input [B,T,D]
    const float* att = (const float*)d_in[1];   // att_score [B,T,1]
    const float* gk  = (const float*)d_in[2];   // gate_kernel [2D,2D]
    const float* gb  = (const float*)d_in[3];   // gate_bias [2D]
    const float* ck  = (const float*)d_in[4];   // cand_kernel [2D,D]
    const float* cb  = (const float*)d_in[5];   // cand_bias [D]
    const int*   sl  = (const int*)d_in[6];     // sequence_length [B,1]
    float* out = (float*)d_out;                 // [B,T,D]

    cudaFuncSetAttribute(pre_mma, cudaFuncAttributeMaxDynamicSharedMemorySize, PRE_SMEM);
    cudaFuncSetAttribute(rec_kernel, cudaFuncAttributeMaxDynamicSharedMemorySize, REC_SMEM);

    prep_w<<<384, 128>>>(gk, ck);
    pre_mma<<<(BB * TT) / 128, 512, PRE_SMEM>>>(x, gb, cb, sl);
    rec_kernel<<<BB / 8, 512, REC_SMEM>>>(att, sl, out);
}